// round 2
// baseline (speedup 1.0000x reference)
#include <cuda_runtime.h>
#include <math.h>

#define NN 1000
#define FF 64
#define SS 192          // B*T snapshots
#define EE 16000
#define CC 10
#define BBATCH 16
#define JTOT 768000     // T*N*F
#define LN_EPS 1e-5f
#define FCHUNKS 192
#define CHUNK_J 4000    // 192*4000 = 768000

// ---------------- scratch (static device globals; no allocation) -------------
__device__ float g_basis[8][SS * NN * FF];   // slots 1..8 (slot0 = x itself)
__device__ float g_h[SS * NN * FF];          // post-LayerNorm activations
__device__ float g_Wcat[576 * 128];          // packed weights: cols 0..63 = z, 64..127 = h
__device__ float g_bcat[128];
__device__ int   g_deg_out[NN], g_deg_in[NN];
__device__ int   g_offA[NN + 1], g_offB[NN + 1];
__device__ int   g_adjA_src[EE];             // prop_out: grouped by dst(col), src=row
__device__ float g_adjA_w[EE];               // 1/deg_out[src]
__device__ int   g_adjB_src[EE];             // prop_in : grouped by row, src=col
__device__ float g_inv_deg_in[NN];
__device__ float g_partial[FCHUNKS * BBATCH * CC];

// ---------------- graph preprocessing ----------------------------------------
__global__ void k_zero_deg() {
    int i = blockIdx.x * blockDim.x + threadIdx.x;
    if (i < NN) { g_deg_out[i] = 0; g_deg_in[i] = 0; }
}

__global__ void k_count(const int* __restrict__ ei) {
    int e = blockIdx.x * blockDim.x + threadIdx.x;
    if (e < EE) {
        atomicAdd(&g_deg_out[ei[e]], 1);        // row = src
        atomicAdd(&g_deg_in[ei[EE + e]], 1);    // col = dst
    }
}

__global__ void k_scan() {   // tiny serial scan, 1 thread
    int a = 0, b = 0;
    for (int n = 0; n < NN; n++) {
        g_offA[n] = a; a += g_deg_in[n];        // listA count[n] = #edges with col==n
        g_offB[n] = b; b += g_deg_out[n];       // listB count[n] = #edges with row==n
        g_inv_deg_in[n] = 1.0f / (float)g_deg_in[n];
    }
    g_offA[NN] = a; g_offB[NN] = b;
}

// one warp per node; ballot-compaction keeps edge order deterministic
__global__ void k_build(const int* __restrict__ ei) {
    int warp = (blockIdx.x * blockDim.x + threadIdx.x) >> 5;
    int lane = threadIdx.x & 31;
    if (warp >= NN) return;
    int n = warp;
    int pa = g_offA[n], pb = g_offB[n];
    for (int e0 = 0; e0 < EE; e0 += 32) {
        int e = e0 + lane;
        int r = ei[e], c = ei[EE + e];
        unsigned mA = __ballot_sync(0xffffffffu, c == n);
        unsigned mB = __ballot_sync(0xffffffffu, r == n);
        if (c == n) {
            int pos = pa + __popc(mA & ((1u << lane) - 1));
            g_adjA_src[pos] = r;
            g_adjA_w[pos] = 1.0f / (float)g_deg_out[r];
        }
        if (r == n) {
            int pos = pb + __popc(mB & ((1u << lane) - 1));
            g_adjB_src[pos] = c;
        }
        pa += __popc(mA); pb += __popc(mB);
    }
}

// pack W_z / W_h (only first 64 input channels matter; h0 == 0)
__global__ void k_packW(const float* __restrict__ Wz, const float* __restrict__ bz,
                        const float* __restrict__ Wh, const float* __restrict__ bh) {
    int i = blockIdx.x * blockDim.x + threadIdx.x;
    if (i < 576 * 128) {
        int rk = i >> 7, col = i & 127;      // rk: 0..575 (K dim), col: output
        int slot = rk >> 6, c = rk & 63;     // slot 0..8, in-channel c
        const float* W = (col < 64) ? Wz : Wh;
        int f = col & 63;
        float v;
        if (slot == 0) {   // Tx0 gets W[0,0] + W[1,0]
            v = W[(0 * 5 + 0) * 128 * 64 + c * 64 + f]
              + W[(1 * 5 + 0) * 128 * 64 + c * 64 + f];
        } else {
            int k = (slot + 1) >> 1;         // slot 1,2 -> k1; 3,4 -> k2; ...
            int dir = (slot - 1) & 1;        // odd slot -> out(0), even -> in(1)
            v = W[(dir * 5 + k) * 128 * 64 + c * 64 + f];
        }
        g_Wcat[rk * 128 + col] = v;
    }
    if (i < 128) g_bcat[i] = (i < 64) ? bz[i] : bh[i - 64];
}

// ---------------- Chebyshev propagation (smem-cached gather) ------------------
// block = (snapshot, direction, feature-half). Caches whole source half-plane
// (1000 nodes x 32 feats = 125KB) in dynamic smem; gathers come from smem.
//
// NOTE on the recurrence: the reference rebinds Tx0 = Tx1o after each k, so
// BOTH directions subtract the OUT-direction previous term:
//   Tx_k_o = 2*P_o(Tx_{k-1}_o) - Tx_{k-2}_o
//   Tx_k_i = 2*P_i(Tx_{k-1}_i) - Tx_{k-2}_o   <-- out-direction prev!
__global__ void k_prop(const float* __restrict__ x, int level) {
    extern __shared__ float sm[];            // NN*32 floats
    int s = blockIdx.x, dir = blockIdx.y, half = blockIdx.z;
    int dst_slot = 2 * level - 1 + dir;      // 1..8
    const float* src;
    const float* prev = nullptr;
    if (level == 1) {
        src = x + (size_t)s * NN * FF;
    } else {
        int ssrc = 2 * (level - 1) - 1 + dir;              // own-direction prev term (propagated)
        src = g_basis[ssrc - 1] + (size_t)s * NN * FF;
        if (level == 2) prev = x + (size_t)s * NN * FF;    // Tx0 = h for both dirs
        else prev = g_basis[(2 * (level - 2) - 1) - 1]     // Tx_{level-2}_OUT for both dirs
                    + (size_t)s * NN * FF;
    }
    for (int i = threadIdx.x; i < NN * 32; i += blockDim.x) {
        int n = i >> 5, f = i & 31;
        sm[i] = src[n * FF + half * 32 + f];
    }
    __syncthreads();

    int lane = threadIdx.x & 31;
    int w = threadIdx.x >> 5;
    int nw = blockDim.x >> 5;
    float* out = g_basis[dst_slot - 1] + (size_t)s * NN * FF;

    for (int n = w; n < NN; n += nw) {
        float acc = 0.0f;
        if (dir == 0) {                       // prop_out: out[n] = sum h[src]/deg_out[src]
            int b = g_offA[n], e = g_offA[n + 1];
            for (int j = b; j < e; j++)
                acc += sm[g_adjA_src[j] * 32 + lane] * g_adjA_w[j];
        } else {                              // prop_in: out[n] = (1/deg_in[n]) * sum h[src]
            int b = g_offB[n], e = g_offB[n + 1];
            for (int j = b; j < e; j++)
                acc += sm[g_adjB_src[j] * 32 + lane];
            acc *= g_inv_deg_in[n];
        }
        float r = (level == 1) ? acc : 2.0f * acc - prev[n * FF + half * 32 + lane];
        out[n * FF + half * 32 + lane] = r;
    }
}

// ---------------- per-snapshot GEMM [1000,576]x[576,128] + gate/LN epilogue ---
__global__ void __launch_bounds__(256) k_gemm(const float* __restrict__ x,
                                              const float* __restrict__ ln_g,
                                              const float* __restrict__ ln_b) {
    __shared__ float SM[8448];
    float* As = SM;                 // [32][65]   (k-major, padded)
    float* Bs = SM + 32 * 65;       // [32][128]
    int s = blockIdx.y;
    int row0 = blockIdx.x * 64;
    int tid = threadIdx.x;
    int ty = tid >> 4, tx = tid & 15;

    float acc[4][8];
    #pragma unroll
    for (int i = 0; i < 4; i++)
        #pragma unroll
        for (int j = 0; j < 8; j++) acc[i][j] = 0.0f;

    for (int ks = 0; ks < 18; ks++) {         // 576 / 32
        int slot = (ks * 32) >> 6;
        int koff = (ks * 32) & 63;
        const float* plane = (slot == 0) ? (x + (size_t)s * NN * FF)
                                         : (g_basis[slot - 1] + (size_t)s * NN * FF);
        #pragma unroll
        for (int j = 0; j < 8; j++) {         // A tile: 64 rows x 32 k
            int idx = tid + j * 256;
            int m = idx >> 5, kk = idx & 31;
            int n = row0 + m;
            As[kk * 65 + m] = (n < NN) ? plane[n * FF + koff + kk] : 0.0f;
        }
        #pragma unroll
        for (int j = 0; j < 16; j++) {        // B tile: 32 k x 128 n
            int idx = tid + j * 256;
            int kk = idx >> 7, col = idx & 127;
            Bs[kk * 128 + col] = g_Wcat[(ks * 32 + kk) * 128 + col];
        }
        __syncthreads();
        #pragma unroll
        for (int kk = 0; kk < 32; kk++) {
            float a[4];
            #pragma unroll
            for (int i = 0; i < 4; i++) a[i] = As[kk * 65 + ty * 4 + i];
            float4 b0 = *(const float4*)&Bs[kk * 128 + tx * 8];
            float4 b1 = *(const float4*)&Bs[kk * 128 + tx * 8 + 4];
            float b[8] = {b0.x, b0.y, b0.z, b0.w, b1.x, b1.y, b1.z, b1.w};
            #pragma unroll
            for (int i = 0; i < 4; i++)
                #pragma unroll
                for (int j = 0; j < 8; j++) acc[i][j] += a[i] * b[j];
        }
        __syncthreads();
    }

    // epilogue: z = sigmoid(Z+bz), t = tanh(H+bh) into smem
    float* smZ = SM;            // [64][65]
    float* smT = SM + 64 * 65;  // [64][65]
    bool isZ = (tx < 8);
    #pragma unroll
    for (int i = 0; i < 4; i++) {
        int r = ty * 4 + i;
        #pragma unroll
        for (int j = 0; j < 8; j++) {
            int col = tx * 8 + j;
            float v = acc[i][j] + g_bcat[col];
            if (isZ) smZ[r * 65 + col] = 1.0f / (1.0f + expf(-v));
            else     smT[r * 65 + (col - 64)] = tanhf(v);
        }
    }
    __syncthreads();

    // gate combine + relu + LayerNorm: 4 threads per node
    int node = tid >> 2, q = tid & 3;
    int n = row0 + node;
    float s1 = 0.0f, s2 = 0.0f;
    #pragma unroll
    for (int f = q * 16; f < q * 16 + 16; f++) {
        float z = smZ[node * 65 + f], t = smT[node * 65 + f];
        float v = fmaxf((1.0f - z) * t, 0.0f);
        s1 += v; s2 += v * v;
    }
    s1 += __shfl_xor_sync(0xffffffffu, s1, 1);
    s1 += __shfl_xor_sync(0xffffffffu, s1, 2);
    s2 += __shfl_xor_sync(0xffffffffu, s2, 1);
    s2 += __shfl_xor_sync(0xffffffffu, s2, 2);
    float mu = s1 * (1.0f / 64.0f);
    float var = s2 * (1.0f / 64.0f) - mu * mu;
    float rstd = rsqrtf(var + LN_EPS);
    if (n < NN) {
        float* o = g_h + (size_t)s * NN * FF + n * FF;
        #pragma unroll
        for (int f = q * 16; f < q * 16 + 16; f++) {
            float z = smZ[node * 65 + f], t = smT[node * 65 + f];
            float v = fmaxf((1.0f - z) * t, 0.0f);
            o[f] = (v - mu) * rstd * ln_g[f] + ln_b[f];
        }
    }
}

// ---------------- final thin GEMM [16,768000] x [768000,10] -------------------
__global__ void __launch_bounds__(256) k_final1(const float* __restrict__ lin_w) {
    int chunk = blockIdx.x;
    int j0 = chunk * CHUNK_J;
    int tid = threadIdx.x;
    int bg = tid >> 6;          // batch-group 0..3 (b = bg*4 .. bg*4+3)
    int kl = tid & 63;          // k lane
    float acc[4][10];
    #pragma unroll
    for (int bi = 0; bi < 4; bi++)
        #pragma unroll
        for (int c = 0; c < 10; c++) acc[bi][c] = 0.0f;

    for (int k = j0 + kl; k < j0 + CHUNK_J; k += 64) {
        float w[10];
        #pragma unroll
        for (int c = 0; c < 10; c++) w[c] = lin_w[(size_t)c * JTOT + k];
        #pragma unroll
        for (int bi = 0; bi < 4; bi++) {
            float h = g_h[(size_t)(bg * 4 + bi) * JTOT + k];
            #pragma unroll
            for (int c = 0; c < 10; c++) acc[bi][c] += h * w[c];
        }
    }
    __shared__ float red[256 * 40];
    #pragma unroll
    for (int bi = 0; bi < 4; bi++)
        #pragma unroll
        for (int c = 0; c < 10; c++) red[tid * 40 + bi * 10 + c] = acc[bi][c];
    __syncthreads();
    if (tid < 160) {
        int b = tid / 10, c = tid % 10;
        int bg2 = b >> 2, bi2 = b & 3;
        float sum = 0.0f;
        for (int l = 0; l < 64; l++)
            sum += red[(bg2 * 64 + l) * 40 + bi2 * 10 + c];
        g_partial[(chunk * BBATCH + b) * CC + c] = sum;
    }
}

__global__ void k_final2(const float* __restrict__ lin_b, float* __restrict__ out) {
    int i = threadIdx.x;
    if (i < BBATCH * CC) {
        int b = i / CC, c = i % CC;
        float s = lin_b[c];
        for (int ch = 0; ch < FCHUNKS; ch++)
            s += g_partial[(ch * BBATCH + b) * CC + c];
        out[b * CC + c] = s;
    }
}

// ---------------- launch ------------------------------------------------------
extern "C" void kernel_launch(void* const* d_in, const int* in_sizes, int n_in,
                              void* d_out, int out_size) {
    const float* x   = (const float*)d_in[0];
    const int*   ei  = (const int*)d_in[1];
    const float* Wz  = (const float*)d_in[2];
    const float* bz  = (const float*)d_in[3];
    // d_in[4] = W_r, d_in[5] = b_r : provably unused (h0 == 0)
    const float* Wh  = (const float*)d_in[6];
    const float* bh  = (const float*)d_in[7];
    const float* lng = (const float*)d_in[8];
    const float* lnb = (const float*)d_in[9];
    const float* lw  = (const float*)d_in[10];
    const float* lb  = (const float*)d_in[11];
    float* out = (float*)d_out;

    cudaFuncSetAttribute(k_prop, cudaFuncAttributeMaxDynamicSharedMemorySize, 131072);

    k_zero_deg<<<1, 1024>>>();
    k_count<<<(EE + 255) / 256, 256>>>(ei);
    k_scan<<<1, 1>>>();
    k_build<<<(NN * 32 + 255) / 256, 256>>>(ei);
    k_packW<<<(576 * 128 + 255) / 256, 256>>>(Wz, bz, Wh, bh);

    for (int lvl = 1; lvl <= 4; lvl++)
        k_prop<<<dim3(SS, 2, 2), 512, NN * 32 * sizeof(float)>>>(x, lvl);

    k_gemm<<<dim3(16, SS), 256>>>(x, lng, lnb);
    k_final1<<<FCHUNKS, 256>>>(lw);
    k_final2<<<1, 192>>>(lb, out);
}

// round 7
// speedup vs baseline: 1.3894x; 1.3894x over previous
#include <cuda_runtime.h>
#include <cuda_bf16.h>
#include <math.h>
#include <stdint.h>

#define NN 1000
#define FF 64
#define SS 192          // B*T snapshots
#define EE 16000
#define CC 10
#define BBATCH 16
#define JTOT 768000     // T*N*F
#define LN_EPS 1e-5f
#define FCHUNKS 192
#define CHUNK_J 4000

// ---------------- scratch (static device globals; no allocation) -------------
__device__ float g_basis[8][SS * NN * FF];
__device__ float g_h[SS * NN * FF];
__device__ __nv_bfloat16 g_Bpack[2][9][128 * 64];  // [hi/lo][slot][swizzled 128n x 64k]
__device__ float g_bcat[128];
__device__ int   g_deg_out[NN], g_deg_in[NN];
__device__ int   g_offA[NN + 1], g_offB[NN + 1];
__device__ int   g_adjA_src[EE];
__device__ float g_adjA_w[EE];
__device__ int   g_adjB_src[EE];
__device__ float g_inv_deg_in[NN];
__device__ float g_partial[FCHUNKS * BBATCH * CC];

// ---------------- helpers -----------------------------------------------------
__device__ __forceinline__ uint32_t smem_u32(const void* p) {
    uint32_t a;
    asm("{ .reg .u64 t; cvta.to.shared.u64 t, %1; cvt.u32.u64 %0, t; }" : "=r"(a) : "l"(p));
    return a;
}
#define SWZ128(o) ((o) ^ (((o) >> 3) & 0x70))

__device__ __forceinline__ void ldsm4(uint32_t* r, uint32_t addr) {
    asm volatile("ldmatrix.sync.aligned.m8n8.x4.shared.b16 {%0,%1,%2,%3}, [%4];"
        : "=r"(r[0]), "=r"(r[1]), "=r"(r[2]), "=r"(r[3]) : "r"(addr));
}

__device__ __forceinline__ void mma_bf16(float* d, const uint32_t* a, const uint32_t* b) {
    asm volatile(
        "mma.sync.aligned.m16n8k16.row.col.f32.bf16.bf16.f32 "
        "{%0,%1,%2,%3}, {%4,%5,%6,%7}, {%8,%9}, {%0,%1,%2,%3};"
        : "+f"(d[0]), "+f"(d[1]), "+f"(d[2]), "+f"(d[3])
        : "r"(a[0]), "r"(a[1]), "r"(a[2]), "r"(a[3]), "r"(b[0]), "r"(b[1]));
}

// ---------------- graph preprocessing ----------------------------------------
__global__ void k_zero_deg() {
    int i = blockIdx.x * blockDim.x + threadIdx.x;
    if (i < NN) { g_deg_out[i] = 0; g_deg_in[i] = 0; }
}

__global__ void k_count(const int* __restrict__ ei) {
    int e = blockIdx.x * blockDim.x + threadIdx.x;
    if (e < EE) {
        atomicAdd(&g_deg_out[ei[e]], 1);
        atomicAdd(&g_deg_in[ei[EE + e]], 1);
    }
}

// parallel exclusive scan, single block of 1024
__global__ void k_scan() {
    __shared__ int sA[1024], sB[1024];
    int i = threadIdx.x;
    int da = (i < NN) ? g_deg_in[i] : 0;
    int db = (i < NN) ? g_deg_out[i] : 0;
    sA[i] = da; sB[i] = db;
    __syncthreads();
    for (int off = 1; off < 1024; off <<= 1) {
        int va = (i >= off) ? sA[i - off] : 0;
        int vb = (i >= off) ? sB[i - off] : 0;
        __syncthreads();
        sA[i] += va; sB[i] += vb;
        __syncthreads();
    }
    if (i < NN) {
        g_offA[i] = sA[i] - da;
        g_offB[i] = sB[i] - db;
        g_inv_deg_in[i] = 1.0f / (float)da;
    }
    if (i == 0) { g_offA[NN] = sA[NN - 1]; g_offB[NN] = sB[NN - 1]; }
}

// deterministic CSR build: stage all edges in smem, one warp per node, ballot compaction
__global__ void k_build(const int* __restrict__ ei) {
    extern __shared__ int2 se[];                   // 16000 x 8B = 128KB
    int tid = threadIdx.x;
    for (int i = tid; i < EE; i += blockDim.x)
        se[i] = make_int2(ei[i], ei[EE + i]);
    __syncthreads();
    int warp = blockIdx.x * (blockDim.x >> 5) + (tid >> 5);
    int lane = tid & 31;
    if (warp >= NN) return;
    int n = warp;
    int pa = g_offA[n], pb = g_offB[n];
    for (int e0 = 0; e0 < EE; e0 += 32) {
        int2 rc = se[e0 + lane];
        unsigned mA = __ballot_sync(0xffffffffu, rc.y == n);
        unsigned mB = __ballot_sync(0xffffffffu, rc.x == n);
        if (rc.y == n) {
            int pos = pa + __popc(mA & ((1u << lane) - 1));
            g_adjA_src[pos] = rc.x;
            g_adjA_w[pos] = 1.0f / (float)g_deg_out[rc.x];
        }
        if (rc.x == n) {
            int pos = pb + __popc(mB & ((1u << lane) - 1));
            g_adjB_src[pos] = rc.y;
        }
        pa += __popc(mA); pb += __popc(mB);
    }
}

// pack weights into bf16 hi/lo images (SW128-swizzled, [n][k] rows of 128B)
__global__ void k_packW(const float* __restrict__ Wz, const float* __restrict__ bz,
                        const float* __restrict__ Wh, const float* __restrict__ bh) {
    int i = blockIdx.x * blockDim.x + threadIdx.x;
    if (i < 128) g_bcat[i] = (i < 64) ? bz[i] : bh[i - 64];
    if (i >= 9 * 8192) return;
    int slot = i >> 13;
    int r = i & 8191;
    int n = r >> 6, k = r & 63;       // n: output col 0..127, k: in-channel within slot
    const float* W = (n < 64) ? Wz : Wh;
    int f = n & 63;
    float v;
    if (slot == 0) {
        v = W[(0 * 5 + 0) * 128 * 64 + k * 64 + f]
          + W[(1 * 5 + 0) * 128 * 64 + k * 64 + f];
    } else {
        int kc = (slot + 1) >> 1;
        int dir = (slot - 1) & 1;
        v = W[(dir * 5 + kc) * 128 * 64 + k * 64 + f];
    }
    __nv_bfloat16 hi = __float2bfloat16(v);
    __nv_bfloat16 lo = __float2bfloat16(v - __bfloat162float(hi));
    uint32_t off = SWZ128((uint32_t)(n * 128 + k * 2));
    g_Bpack[0][slot][off >> 1] = hi;
    g_Bpack[1][slot][off >> 1] = lo;
}

// ---------------- Chebyshev propagation (smem-cached gather) ------------------
__global__ void k_prop(const float* __restrict__ x, int level) {
    extern __shared__ float sm[];
    int s = blockIdx.x, dir = blockIdx.y, half = blockIdx.z;
    int dst_slot = 2 * level - 1 + dir;
    const float* src;
    const float* prev = nullptr;
    if (level == 1) {
        src = x + (size_t)s * NN * FF;
    } else {
        int ssrc = 2 * (level - 1) - 1 + dir;
        src = g_basis[ssrc - 1] + (size_t)s * NN * FF;
        if (level == 2) prev = x + (size_t)s * NN * FF;
        else prev = g_basis[(2 * (level - 2) - 1) - 1] + (size_t)s * NN * FF;
    }
    for (int i = threadIdx.x; i < NN * 32; i += blockDim.x) {
        int n = i >> 5, f = i & 31;
        sm[i] = src[n * FF + half * 32 + f];
    }
    __syncthreads();

    int lane = threadIdx.x & 31;
    int w = threadIdx.x >> 5;
    int nw = blockDim.x >> 5;
    float* out = g_basis[dst_slot - 1] + (size_t)s * NN * FF;

    for (int n = w; n < NN; n += nw) {
        float acc = 0.0f;
        if (dir == 0) {
            int b = g_offA[n], e = g_offA[n + 1];
            for (int j = b; j < e; j++)
                acc += sm[g_adjA_src[j] * 32 + lane] * g_adjA_w[j];
        } else {
            int b = g_offB[n], e = g_offB[n + 1];
            for (int j = b; j < e; j++)
                acc += sm[g_adjB_src[j] * 32 + lane];
            acc *= g_inv_deg_in[n];
        }
        float r = (level == 1) ? acc : 2.0f * acc - prev[n * FF + half * 32 + lane];
        out[n * FF + half * 32 + lane] = r;
    }
}

// ---------------- mma.sync bf16 GEMM + fused gate/LN epilogue -----------------
// Block: 256 thr = 8 warps; one (snapshot, 128-row tile). Warp w: rows w*16..+16,
// all 128 cols (16 n-tiles of 8). 3-pass bf16 split, fp32 accum in registers.
#define SM_AHI 0
#define SM_ALO 16384
#define SM_BHI 32768
#define SM_BLO 49152
#define SM_TOTAL_GEMM 65536

__global__ void __launch_bounds__(256, 1) k_gemm_mma(const float* __restrict__ x,
                                                     const float* __restrict__ ln_g,
                                                     const float* __restrict__ ln_b) {
    extern __shared__ char smem[];
    uint32_t sb = smem_u32(smem);
    const int tid = threadIdx.x;
    const int wid = tid >> 5, lane = tid & 31;
    const int s = blockIdx.x >> 3;
    const int row0 = (blockIdx.x & 7) << 7;
    const int m0 = wid << 4;

    float acc[16][4];
    #pragma unroll
    for (int t = 0; t < 16; t++)
        #pragma unroll
        for (int c = 0; c < 4; c++) acc[t][c] = 0.0f;

    // ldmatrix lane-address bases (byte offsets before swizzle)
    const uint32_t a_rowoff = (uint32_t)((m0 + (lane & 15)) * 128 + ((lane >> 4) * 16));
    const uint32_t b_rowoff = (uint32_t)((((lane >> 4) * 8 + (lane & 7)) * 128) + (((lane >> 3) & 1) * 16));

    for (int slot = 0; slot < 9; slot++) {
        __syncthreads();
        const float* plane = (slot == 0) ? (x + (size_t)s * NN * FF)
                                         : (g_basis[slot - 1] + (size_t)s * NN * FF);
        // convert A slot: 128 rows x 64 k fp32 -> bf16 hi/lo, SW128-swizzled
        #pragma unroll
        for (int i = 0; i < 8; i++) {
            int j = tid + i * 256;
            int m = j >> 4, kq = j & 15;
            int node = row0 + m;
            float4 v = (node < NN) ? *(const float4*)(plane + (size_t)node * FF + kq * 4)
                                   : make_float4(0.f, 0.f, 0.f, 0.f);
            __nv_bfloat16 h0 = __float2bfloat16(v.x);
            __nv_bfloat16 h1 = __float2bfloat16(v.y);
            __nv_bfloat16 h2 = __float2bfloat16(v.z);
            __nv_bfloat16 h3 = __float2bfloat16(v.w);
            __nv_bfloat16 l0 = __float2bfloat16(v.x - __bfloat162float(h0));
            __nv_bfloat16 l1 = __float2bfloat16(v.y - __bfloat162float(h1));
            __nv_bfloat16 l2 = __float2bfloat16(v.z - __bfloat162float(h2));
            __nv_bfloat16 l3 = __float2bfloat16(v.w - __bfloat162float(h3));
            uint32_t off = SWZ128((uint32_t)(m * 128 + kq * 8));
            *(__nv_bfloat162*)(smem + SM_AHI + off)     = __halves2bfloat162(h0, h1);
            *(__nv_bfloat162*)(smem + SM_AHI + off + 4) = __halves2bfloat162(h2, h3);
            *(__nv_bfloat162*)(smem + SM_ALO + off)     = __halves2bfloat162(l0, l1);
            *(__nv_bfloat162*)(smem + SM_ALO + off + 4) = __halves2bfloat162(l2, l3);
        }
        // copy B slot (already-swizzled images): 2 x 16KB
        {
            const uint4* srcH = (const uint4*)&g_Bpack[0][slot][0];
            const uint4* srcL = (const uint4*)&g_Bpack[1][slot][0];
            #pragma unroll
            for (int i = 0; i < 4; i++) {
                int j = tid + i * 256;
                ((uint4*)(smem + SM_BHI))[j] = srcH[j];
                ((uint4*)(smem + SM_BLO))[j] = srcL[j];
            }
        }
        __syncthreads();

        #pragma unroll
        for (int kk = 0; kk < 4; kk++) {
            const uint32_t kbase = kk * 32;
            uint32_t aAh[4], aAl[4];
            ldsm4(aAh, sb + SM_AHI + SWZ128(a_rowoff + kbase));
            ldsm4(aAl, sb + SM_ALO + SWZ128(a_rowoff + kbase));
            uint32_t bF[8][4];
            #pragma unroll
            for (int p = 0; p < 8; p++)
                ldsm4(bF[p], sb + SM_BHI + SWZ128(b_rowoff + p * 2048 + kbase));
            #pragma unroll
            for (int t = 0; t < 16; t++) {
                const uint32_t* bf = &bF[t >> 1][(t & 1) * 2];
                mma_bf16(acc[t], aAh, bf);     // Ahi * Bhi
                mma_bf16(acc[t], aAl, bf);     // Alo * Bhi
            }
            #pragma unroll
            for (int p = 0; p < 8; p++)
                ldsm4(bF[p], sb + SM_BLO + SWZ128(b_rowoff + p * 2048 + kbase));
            #pragma unroll
            for (int t = 0; t < 16; t++)
                mma_bf16(acc[t], aAh, &bF[t >> 1][(t & 1) * 2]);   // Ahi * Blo
        }
    }

    // fused epilogue: gates + relu + LayerNorm, all register/shfl local
    // c-frag: c0,c1 = (row rl, col, col+1); c2,c3 = (row rl+8, col, col+1)
    int q = lane & 3, rl = lane >> 2;
    #pragma unroll
    for (int h = 0; h < 2; h++) {
        float s1 = 0.f, s2 = 0.f;
        float vals[16];
        #pragma unroll
        for (int j = 0; j < 8; j++) {
            #pragma unroll
            for (int p = 0; p < 2; p++) {
                int col = j * 8 + q * 2 + p;
                float zc = acc[j][h * 2 + p] + g_bcat[col];
                float tc = acc[8 + j][h * 2 + p] + g_bcat[64 + col];
                float z = 1.0f / (1.0f + expf(-zc));
                float tt = tanhf(tc);
                float v = fmaxf((1.0f - z) * tt, 0.0f);
                vals[j * 2 + p] = v; s1 += v; s2 += v * v;
            }
        }
        s1 += __shfl_xor_sync(0xffffffffu, s1, 1);
        s1 += __shfl_xor_sync(0xffffffffu, s1, 2);
        s2 += __shfl_xor_sync(0xffffffffu, s2, 1);
        s2 += __shfl_xor_sync(0xffffffffu, s2, 2);
        float mu = s1 * (1.0f / 64.0f);
        float var = s2 * (1.0f / 64.0f) - mu * mu;
        float rstd = rsqrtf(var + LN_EPS);
        int node = row0 + m0 + rl + h * 8;
        if (node < NN) {
            float* o = g_h + ((size_t)s * NN + node) * FF;
            #pragma unroll
            for (int j = 0; j < 8; j++) {
                int col = j * 8 + q * 2;
                float2 w;
                w.x = (vals[j * 2 + 0] - mu) * rstd * ln_g[col] + ln_b[col];
                w.y = (vals[j * 2 + 1] - mu) * rstd * ln_g[col + 1] + ln_b[col + 1];
                *(float2*)(o + col) = w;
            }
        }
    }
}

// ---------------- final thin GEMM [16,768000] x [768000,10] -------------------
__global__ void __launch_bounds__(256) k_final1(const float* __restrict__ lin_w) {
    int chunk = blockIdx.x;
    int j0 = chunk * CHUNK_J;
    int tid = threadIdx.x;
    int bg = tid >> 6;
    int kl = tid & 63;
    float acc[4][10];
    #pragma unroll
    for (int bi = 0; bi < 4; bi++)
        #pragma unroll
        for (int c = 0; c < 10; c++) acc[bi][c] = 0.0f;

    for (int k = j0 + kl; k < j0 + CHUNK_J; k += 64) {
        float w[10];
        #pragma unroll
        for (int c = 0; c < 10; c++) w[c] = lin_w[(size_t)c * JTOT + k];
        #pragma unroll
        for (int bi = 0; bi < 4; bi++) {
            float h = g_h[(size_t)(bg * 4 + bi) * JTOT + k];
            #pragma unroll
            for (int c = 0; c < 10; c++) acc[bi][c] += h * w[c];
        }
    }
    __shared__ float red[256 * 40];
    #pragma unroll
    for (int bi = 0; bi < 4; bi++)
        #pragma unroll
        for (int c = 0; c < 10; c++) red[tid * 40 + bi * 10 + c] = acc[bi][c];
    __syncthreads();
    if (tid < 160) {
        int b = tid / 10, c = tid % 10;
        int bg2 = b >> 2, bi2 = b & 3;
        float sum = 0.0f;
        for (int l = 0; l < 64; l++)
            sum += red[(bg2 * 64 + l) * 40 + bi2 * 10 + c];
        g_partial[(chunk * BBATCH + b) * CC + c] = sum;
    }
}

__global__ void k_final2(const float* __restrict__ lin_b, float* __restrict__ out) {
    int i = threadIdx.x;
    if (i < BBATCH * CC) {
        int b = i / CC, c = i % CC;
        float s = lin_b[c];
        for (int ch = 0; ch < FCHUNKS; ch++)
            s += g_partial[(ch * BBATCH + b) * CC + c];
        out[b * CC + c] = s;
    }
}

// ---------------- launch ------------------------------------------------------
extern "C" void kernel_launch(void* const* d_in, const int* in_sizes, int n_in,
                              void* d_out, int out_size) {
    const float* x   = (const float*)d_in[0];
    const int*   ei  = (const int*)d_in[1];
    const float* Wz  = (const float*)d_in[2];
    const float* bz  = (const float*)d_in[3];
    // d_in[4]=W_r, d_in[5]=b_r provably unused (h0 == 0)
    const float* Wh  = (const float*)d_in[6];
    const float* bh  = (const float*)d_in[7];
    const float* lng = (const float*)d_in[8];
    const float* lnb = (const float*)d_in[9];
    const float* lw  = (const float*)d_in[10];
    const float* lb  = (const float*)d_in[11];
    float* out = (float*)d_out;

    cudaFuncSetAttribute(k_prop, cudaFuncAttributeMaxDynamicSharedMemorySize, 131072);
    cudaFuncSetAttribute(k_build, cudaFuncAttributeMaxDynamicSharedMemorySize, EE * 8);
    cudaFuncSetAttribute(k_gemm_mma, cudaFuncAttributeMaxDynamicSharedMemorySize, SM_TOTAL_GEMM);

    k_zero_deg<<<1, 1024>>>();
    k_count<<<(EE + 255) / 256, 256>>>(ei);
    k_scan<<<1, 1024>>>();
    k_build<<<(NN + 7) / 8, 256, EE * 8>>>(ei);
    k_packW<<<(9 * 8192 + 255) / 256, 256>>>(Wz, bz, Wh, bh);

    for (int lvl = 1; lvl <= 4; lvl++)
        k_prop<<<dim3(SS, 2, 2), 512, NN * 32 * sizeof(float)>>>(x, lvl);

    k_gemm_mma<<<SS * 8, 256, SM_TOTAL_GEMM>>>(x, lng, lnb);
    k_final1<<<FCHUNKS, 256>>>(lw);
    k_final2<<<1, 192>>>(lb, out);
}